// round 2
// baseline (speedup 1.0000x reference)
#include <cuda_runtime.h>
#include <cuda_bf16.h>
#include <math.h>

// Problem constants (fixed by the reference)
#define BQ 2
#define TT 2048
#define CC 1024
#define HH 16
#define DD 64
#define MM (BQ*TT)   // 4096 rows

// Scratch (device globals: allocation-free rule)
__device__ float g_q[(size_t)MM*CC];
__device__ float g_k[(size_t)MM*CC];
__device__ float g_v[(size_t)MM*CC];
__device__ float g_Q[(size_t)MM*CC];   // [B,H,T,D], rope applied
__device__ float g_K[(size_t)MM*CC];   // [B,H,T,D], rope applied
__device__ float g_V[(size_t)MM*CC];   // [B,H,T,D]
__device__ float g_att[(size_t)MM*CC]; // [B,T,C] attention output

// ---------------------------------------------------------------------------
// SGEMM: C[M,N] = A[M,K] @ W[K,N] + bias  (M=4096, N=K=1024 hardcoded)
// 128x128x8 tile, 256 threads, 8x8 microtile.
// srcFlag: 0 -> Aext, 1 -> g_att ; dstFlag: 0/1/2 -> g_q/g_k/g_v, 3 -> Cext
// ---------------------------------------------------------------------------
#define GBM 128
#define GBN 128
#define GBK 8

__global__ __launch_bounds__(256, 2) void sgemm_bias(
    const float* __restrict__ Aext, const float* __restrict__ W,
    const float* __restrict__ bias, float* __restrict__ Cext,
    int srcFlag, int dstFlag)
{
    const float* A = srcFlag ? g_att : Aext;
    float* C = (dstFlag == 0) ? g_q : (dstFlag == 1) ? g_k
             : (dstFlag == 2) ? g_v : Cext;

    __shared__ __align__(16) float As[GBK][GBM]; // stored K-major transposed
    __shared__ __align__(16) float Bs[GBK][GBN];

    const int bm = blockIdx.y * GBM;
    const int bn = blockIdx.x * GBN;
    const int tid = threadIdx.x;

    const int arow = tid >> 1;          // 0..127
    const int acol = (tid & 1) << 2;    // 0 or 4
    const int brow = tid >> 5;          // 0..7
    const int bcol = (tid & 31) << 2;   // 0..124
    const int tr = (tid >> 4) << 3;     // 0..120
    const int tc = (tid & 15) << 3;     // 0..120

    const int K = CC, N = CC;

    float acc[8][8];
#pragma unroll
    for (int i = 0; i < 8; i++)
#pragma unroll
        for (int j = 0; j < 8; j++) acc[i][j] = 0.f;

    const float* Aptr = A + (size_t)(bm + arow) * K + acol;
    const float* Wptr = W + (size_t)brow * N + bn + bcol;

    for (int k0 = 0; k0 < K; k0 += GBK) {
        float4 a = *(const float4*)(Aptr + k0);
        As[acol + 0][arow] = a.x;
        As[acol + 1][arow] = a.y;
        As[acol + 2][arow] = a.z;
        As[acol + 3][arow] = a.w;
        *(float4*)&Bs[brow][bcol] = *(const float4*)(Wptr + (size_t)k0 * N);
        __syncthreads();

#pragma unroll
        for (int k = 0; k < GBK; k++) {
            float4 a0 = *(const float4*)&As[k][tr];
            float4 a1 = *(const float4*)&As[k][tr + 4];
            float4 b0 = *(const float4*)&Bs[k][tc];
            float4 b1 = *(const float4*)&Bs[k][tc + 4];
            float ra[8] = {a0.x, a0.y, a0.z, a0.w, a1.x, a1.y, a1.z, a1.w};
            float rb[8] = {b0.x, b0.y, b0.z, b0.w, b1.x, b1.y, b1.z, b1.w};
#pragma unroll
            for (int i = 0; i < 8; i++)
#pragma unroll
                for (int j = 0; j < 8; j++)
                    acc[i][j] = fmaf(ra[i], rb[j], acc[i][j]);
        }
        __syncthreads();
    }

#pragma unroll
    for (int i = 0; i < 8; i++) {
        float* crow = C + (size_t)(bm + tr + i) * N + bn + tc;
#pragma unroll
        for (int j = 0; j < 8; j++)
            crow[j] = acc[i][j] + bias[bn + tc + j];
    }
}

// ---------------------------------------------------------------------------
// RoPE + transpose [B,T,H,D] -> [B,H,T,D]. One thread per (b,h,t,j<16).
// Handles rope pair (j, j+16), pass dims (j+32, j+48) for q/k, 4 v copies.
// ---------------------------------------------------------------------------
__global__ void rope_transpose_kernel()
{
    int idx = blockIdx.x * blockDim.x + threadIdx.x;
    if (idx >= BQ * HH * TT * 16) return;
    int j = idx & 15;
    int t = (idx >> 4) & (TT - 1);
    int h = (idx >> 15) & (HH - 1);
    int b = idx >> 19;

    const size_t src = ((size_t)(b * TT + t)) * CC + h * DD;
    const size_t dst = ((size_t)((b * HH + h) * TT + t)) * DD;

    // inv_freq[j] = 10000^(-j/16); log2(10000)/16 = 0.8304820237218405
    float inv = exp2f(-(float)j * 0.8304820237218405f);
    float ang = (float)t * inv;
    float sn, cs;
    sincosf(ang, &sn, &cs);

    float q0 = g_q[src + j], q1 = g_q[src + j + 16];
    g_Q[dst + j]      = q0 * cs - q1 * sn;
    g_Q[dst + j + 16] = q1 * cs + q0 * sn;

    float k0 = g_k[src + j], k1 = g_k[src + j + 16];
    g_K[dst + j]      = k0 * cs - k1 * sn;
    g_K[dst + j + 16] = k1 * cs + k0 * sn;

    g_Q[dst + j + 32] = g_q[src + j + 32];
    g_Q[dst + j + 48] = g_q[src + j + 48];
    g_K[dst + j + 32] = g_k[src + j + 32];
    g_K[dst + j + 48] = g_k[src + j + 48];

    g_V[dst + j]      = g_v[src + j];
    g_V[dst + j + 16] = g_v[src + j + 16];
    g_V[dst + j + 32] = g_v[src + j + 32];
    g_V[dst + j + 48] = g_v[src + j + 48];
}

// ---------------------------------------------------------------------------
// Flash attention (fp32, causal). 64 Q rows x 64 K cols per tile, D=64.
// 256 threads: 16x16 grid, 4x4 microtile. Online softmax in registers,
// row reductions via half-warp shuffles.
// smem: Qs[64][64] | KsT[64][65] (K transposed, padded) | Vs[64][64] | Ps[64][64]
// ---------------------------------------------------------------------------
#define ATT_SMEM_FLOATS (4096 + 4160 + 4096 + 4096)

__global__ __launch_bounds__(256) void attn_kernel()
{
    extern __shared__ __align__(16) float sm[];
    float* Qs  = sm;                 // 64*64
    float* KsT = sm + 4096;          // 64*65 (d-major, padded)
    float* Vs  = KsT + 4160;         // 64*64
    float* Ps  = Vs + 4096;          // 64*64

    const int bh = blockIdx.y;       // b*16 + h
    const int qb = blockIdx.x;       // query tile index

    const float* Qg = g_Q + (size_t)bh * TT * DD + (size_t)qb * 64 * DD;
    const float* Kg = g_K + (size_t)bh * TT * DD;
    const float* Vg = g_V + (size_t)bh * TT * DD;

    const int tid = threadIdx.x;
    const int tx = tid & 15, ty = tid >> 4;
    const int r0 = ty << 2, c0 = tx << 2;

    // Load Q tile
#pragma unroll
    for (int i = 0; i < 4; i++) {
        int idx = tid + i * 256;
        int r = idx >> 4, d4 = (idx & 15) << 2;
        *(float4*)&Qs[r * 64 + d4] = *(const float4*)&Qg[r * 64 + d4];
    }

    float m[4], l[4], acc[4][4];
#pragma unroll
    for (int i = 0; i < 4; i++) {
        m[i] = -3.0e38f; l[i] = 0.f;
#pragma unroll
        for (int j = 0; j < 4; j++) acc[i][j] = 0.f;
    }

    for (int jt = 0; jt <= qb; jt++) {
        __syncthreads();
        const float* Kt = Kg + (size_t)jt * 64 * DD;
        const float* Vt = Vg + (size_t)jt * 64 * DD;
#pragma unroll
        for (int i = 0; i < 4; i++) {
            int idx = tid + i * 256;
            int r = idx >> 4, d4 = (idx & 15) << 2;
            float4 kv = *(const float4*)&Kt[r * 64 + d4];
            KsT[(d4 + 0) * 65 + r] = kv.x;
            KsT[(d4 + 1) * 65 + r] = kv.y;
            KsT[(d4 + 2) * 65 + r] = kv.z;
            KsT[(d4 + 3) * 65 + r] = kv.w;
            *(float4*)&Vs[r * 64 + d4] = *(const float4*)&Vt[r * 64 + d4];
        }
        __syncthreads();

        // S = Q K^T
        float s[4][4];
#pragma unroll
        for (int i = 0; i < 4; i++)
#pragma unroll
            for (int j = 0; j < 4; j++) s[i][j] = 0.f;

#pragma unroll 8
        for (int d = 0; d < 64; d++) {
            float qa[4], kb[4];
#pragma unroll
            for (int i = 0; i < 4; i++) qa[i] = Qs[(r0 + i) * 64 + d];
#pragma unroll
            for (int j = 0; j < 4; j++) kb[j] = KsT[d * 65 + c0 + j];
#pragma unroll
            for (int i = 0; i < 4; i++)
#pragma unroll
                for (int j = 0; j < 4; j++)
                    s[i][j] = fmaf(qa[i], kb[j], s[i][j]);
        }

        // scale + causal mask (only the diagonal tile needs masking)
        if (jt == qb) {
#pragma unroll
            for (int i = 0; i < 4; i++)
#pragma unroll
                for (int j = 0; j < 4; j++)
                    s[i][j] = (c0 + j <= r0 + i) ? s[i][j] * 0.125f : -1.0e30f;
        } else {
#pragma unroll
            for (int i = 0; i < 4; i++)
#pragma unroll
                for (int j = 0; j < 4; j++) s[i][j] *= 0.125f;
        }

        // online softmax per row (16-thread row groups share half a warp)
#pragma unroll
        for (int i = 0; i < 4; i++) {
            float tm = fmaxf(fmaxf(s[i][0], s[i][1]), fmaxf(s[i][2], s[i][3]));
            tm = fmaxf(tm, __shfl_xor_sync(0xffffffffu, tm, 1));
            tm = fmaxf(tm, __shfl_xor_sync(0xffffffffu, tm, 2));
            tm = fmaxf(tm, __shfl_xor_sync(0xffffffffu, tm, 4));
            tm = fmaxf(tm, __shfl_xor_sync(0xffffffffu, tm, 8));
            float mn = fmaxf(m[i], tm);
            float rs = 0.f;
#pragma unroll
            for (int j = 0; j < 4; j++) {
                s[i][j] = __expf(s[i][j] - mn);
                rs += s[i][j];
            }
            rs += __shfl_xor_sync(0xffffffffu, rs, 1);
            rs += __shfl_xor_sync(0xffffffffu, rs, 2);
            rs += __shfl_xor_sync(0xffffffffu, rs, 4);
            rs += __shfl_xor_sync(0xffffffffu, rs, 8);
            float al = __expf(m[i] - mn);
            l[i] = l[i] * al + rs;
            m[i] = mn;
#pragma unroll
            for (int j = 0; j < 4; j++) acc[i][j] *= al;
#pragma unroll
            for (int j = 0; j < 4; j++) Ps[(r0 + i) * 64 + c0 + j] = s[i][j];
        }
        __syncthreads();

        // O += P @ V
#pragma unroll 8
        for (int kk = 0; kk < 64; kk++) {
            float pr[4], vr[4];
#pragma unroll
            for (int i = 0; i < 4; i++) pr[i] = Ps[(r0 + i) * 64 + kk];
#pragma unroll
            for (int j = 0; j < 4; j++) vr[j] = Vs[kk * 64 + c0 + j];
#pragma unroll
            for (int i = 0; i < 4; i++)
#pragma unroll
                for (int j = 0; j < 4; j++)
                    acc[i][j] = fmaf(pr[i], vr[j], acc[i][j]);
        }
    }

    // normalize + write to g_att as [B,T,C]  (C index = h*64 + d)
    const int b = bh >> 4, h = bh & 15;
#pragma unroll
    for (int i = 0; i < 4; i++) {
        float invl = 1.f / l[i];
        size_t row = ((size_t)(b * TT + qb * 64 + r0 + i)) * CC + h * DD + c0;
#pragma unroll
        for (int j = 0; j < 4; j++)
            g_att[row + j] = acc[i][j] * invl;
    }
}

// ---------------------------------------------------------------------------
extern "C" void kernel_launch(void* const* d_in, const int* in_sizes, int n_in,
                              void* d_out, int out_size)
{
    const float* x  = (const float*)d_in[0];
    const float* Wq = (const float*)d_in[1];
    const float* bq = (const float*)d_in[2];
    const float* Wk = (const float*)d_in[3];
    const float* bk = (const float*)d_in[4];
    const float* Wv = (const float*)d_in[5];
    const float* bv = (const float*)d_in[6];
    const float* Wo = (const float*)d_in[7];
    const float* bo = (const float*)d_in[8];
    float* out = (float*)d_out;

    dim3 gg(CC / GBN, MM / GBM); // (8, 32)

    sgemm_bias<<<gg, 256>>>(x, Wq, bq, nullptr, 0, 0);
    sgemm_bias<<<gg, 256>>>(x, Wk, bk, nullptr, 0, 1);
    sgemm_bias<<<gg, 256>>>(x, Wv, bv, nullptr, 0, 2);

    rope_transpose_kernel<<<(BQ * HH * TT * 16) / 256, 256>>>();

    cudaFuncSetAttribute(attn_kernel,
                         cudaFuncAttributeMaxDynamicSharedMemorySize,
                         ATT_SMEM_FLOATS * sizeof(float));
    attn_kernel<<<dim3(TT / 64, BQ * HH), 256,
                  ATT_SMEM_FLOATS * sizeof(float)>>>();

    sgemm_bias<<<gg, 256>>>(nullptr, Wo, bo, out, 1, 3);
}

// round 4
// speedup vs baseline: 1.7597x; 1.7597x over previous
#include <cuda_runtime.h>
#include <cuda_bf16.h>
#include <math.h>

// Problem constants (fixed by the reference)
#define BQ 2
#define TT 2048
#define CC 1024
#define HH 16
#define DD 64
#define MM (BQ*TT)   // 4096 rows

// Scratch (device globals: allocation-free rule)
__device__ float g_q[(size_t)MM*CC];
__device__ float g_k[(size_t)MM*CC];
__device__ float g_v[(size_t)MM*CC];
__device__ float g_Q[(size_t)MM*CC];   // [B,H,T,D], rope applied
__device__ float g_K[(size_t)MM*CC];   // [B,H,T,D], rope applied
__device__ float g_V[(size_t)MM*CC];   // [B,H,T,D]
__device__ float g_att[(size_t)MM*CC]; // [B,T,C] attention output

// ---------------------------------------------------------------------------
// TF32 tensor-core GEMM: C[M,N] = A[M,K] @ W[K,N] + bias
// M=4096, N=K=1024. 128x128x32 CTA tile, 256 threads (8 warps),
// warp tile 64x32 as 4x4 m16n8k8 mma tiles. cp.async + ldmatrix.
// srcFlag: 0 -> Aext, 1 -> g_att ; dstFlag: 0/1/2 -> g_q/g_k/g_v, 3 -> Cext
// ---------------------------------------------------------------------------
#define GBM 128
#define GBN 128
#define GBK 32
#define AS_STRIDE 36    // pad 32->36 floats: ldmatrix conflict-free (144B rows)
#define BS_STRIDE 136   // pad 128->136 floats: B-frag LDS conflict-free

__device__ __forceinline__ void cp16(void* dst, const void* src) {
    unsigned d = (unsigned)__cvta_generic_to_shared(dst);
    asm volatile("cp.async.cg.shared.global [%0], [%1], 16;\n" :: "r"(d), "l"(src));
}

__global__ __launch_bounds__(256, 2) void gemm_tf32(
    const float* __restrict__ Aext, const float* __restrict__ W,
    const float* __restrict__ bias, float* __restrict__ Cext,
    int srcFlag, int dstFlag)
{
    const float* A = srcFlag ? g_att : Aext;
    float* C = (dstFlag == 0) ? g_q : (dstFlag == 1) ? g_k
             : (dstFlag == 2) ? g_v : Cext;

    __shared__ __align__(16) float As[GBM * AS_STRIDE]; // [128][36]
    __shared__ __align__(16) float Bs[GBK * BS_STRIDE]; // [32][136]

    const int tid  = threadIdx.x;
    const int lane = tid & 31;
    const int w    = tid >> 5;
    const int wr   = w >> 2;   // 0..1
    const int wc   = w & 3;    // 0..3
    const int bm   = blockIdx.y * GBM;
    const int bn   = blockIdx.x * GBN;

    float c[4][4][4];
#pragma unroll
    for (int mt = 0; mt < 4; mt++)
#pragma unroll
        for (int nt = 0; nt < 4; nt++)
#pragma unroll
            for (int j = 0; j < 4; j++) c[mt][nt][j] = 0.f;

    // ldmatrix per-lane source row/col offsets within the warp's A tile
    const int lq = lane >> 3;  // matrix index 0..3
    const int lr = lane & 7;   // row within 8x8 matrix
    const int a_row_off = wr * 64 + lr + 8 * (lq & 1);
    const int a_col_off = 4 * (lq >> 1);

    for (int kt = 0; kt < CC / GBK; kt++) {
        // ---- load tiles via cp.async ----
#pragma unroll
        for (int i = 0; i < 4; i++) {
            int f = tid + i * 256;          // 0..1023
            int row = f >> 3, c4 = f & 7;   // A: 128 rows x 8 float4
            cp16(&As[row * AS_STRIDE + c4 * 4],
                 A + (size_t)(bm + row) * CC + kt * GBK + c4 * 4);
        }
#pragma unroll
        for (int i = 0; i < 4; i++) {
            int f = tid + i * 256;
            int k = f >> 5, c4 = f & 31;    // B: 32 rows x 32 float4
            cp16(&Bs[k * BS_STRIDE + c4 * 4],
                 W + (size_t)(kt * GBK + k) * CC + bn + c4 * 4);
        }
        asm volatile("cp.async.commit_group;\n");
        asm volatile("cp.async.wait_group 0;\n");
        __syncthreads();

        // ---- compute ----
#pragma unroll
        for (int ks = 0; ks < 4; ks++) {
            unsigned a[4][4];
#pragma unroll
            for (int mt = 0; mt < 4; mt++) {
                unsigned addr = (unsigned)__cvta_generic_to_shared(
                    &As[(a_row_off + mt * 16) * AS_STRIDE + ks * 8 + a_col_off]);
                asm volatile(
                    "ldmatrix.sync.aligned.m8n8.x4.shared.b16 {%0,%1,%2,%3}, [%4];\n"
                    : "=r"(a[mt][0]), "=r"(a[mt][1]), "=r"(a[mt][2]), "=r"(a[mt][3])
                    : "r"(addr));
#pragma unroll
                for (int j = 0; j < 4; j++)
                    asm volatile("cvt.rna.tf32.f32 %0, %0;\n" : "+r"(a[mt][j]));
            }
#pragma unroll
            for (int nt = 0; nt < 4; nt++) {
                int n = wc * 32 + nt * 8 + (lane >> 2);
                int k = ks * 8 + (lane & 3);
                unsigned b0 = __float_as_uint(Bs[k * BS_STRIDE + n]);
                unsigned b1 = __float_as_uint(Bs[(k + 4) * BS_STRIDE + n]);
                asm volatile("cvt.rna.tf32.f32 %0, %0;\n" : "+r"(b0));
                asm volatile("cvt.rna.tf32.f32 %0, %0;\n" : "+r"(b1));
#pragma unroll
                for (int mt = 0; mt < 4; mt++) {
                    asm volatile(
                        "mma.sync.aligned.m16n8k8.row.col.f32.tf32.tf32.f32 "
                        "{%0,%1,%2,%3}, {%4,%5,%6,%7}, {%8,%9}, {%0,%1,%2,%3};\n"
                        : "+f"(c[mt][nt][0]), "+f"(c[mt][nt][1]),
                          "+f"(c[mt][nt][2]), "+f"(c[mt][nt][3])
                        : "r"(a[mt][0]), "r"(a[mt][1]), "r"(a[mt][2]), "r"(a[mt][3]),
                          "r"(b0), "r"(b1));
                }
            }
        }
        __syncthreads();
    }

    // ---- epilogue: C fragment layout c0:(r, 2c) c1:(r, 2c+1) c2:(r+8,..) ----
#pragma unroll
    for (int mt = 0; mt < 4; mt++) {
        int row = bm + wr * 64 + mt * 16 + (lane >> 2);
#pragma unroll
        for (int nt = 0; nt < 4; nt++) {
            int col = bn + wc * 32 + nt * 8 + 2 * (lane & 3);
            float b0 = bias[col], b1 = bias[col + 1];
            float2 v0 = make_float2(c[mt][nt][0] + b0, c[mt][nt][1] + b1);
            float2 v1 = make_float2(c[mt][nt][2] + b0, c[mt][nt][3] + b1);
            *(float2*)&C[(size_t)row * CC + col] = v0;
            *(float2*)&C[(size_t)(row + 8) * CC + col] = v1;
        }
    }
}

// ---------------------------------------------------------------------------
// RoPE + transpose [B,T,H,D] -> [B,H,T,D]. One thread per (b,h,t,j<16).
// ---------------------------------------------------------------------------
__global__ void rope_transpose_kernel()
{
    int idx = blockIdx.x * blockDim.x + threadIdx.x;
    if (idx >= BQ * HH * TT * 16) return;
    int j = idx & 15;
    int t = (idx >> 4) & (TT - 1);
    int h = (idx >> 15) & (HH - 1);
    int b = idx >> 19;

    const size_t src = ((size_t)(b * TT + t)) * CC + h * DD;
    const size_t dst = ((size_t)((b * HH + h) * TT + t)) * DD;

    // inv_freq[j] = 10000^(-j/16); log2(10000)/16 = 0.8304820237218405
    float inv = exp2f(-(float)j * 0.8304820237218405f);
    float ang = (float)t * inv;
    float sn, cs;
    sincosf(ang, &sn, &cs);

    float q0 = g_q[src + j], q1 = g_q[src + j + 16];
    g_Q[dst + j]      = q0 * cs - q1 * sn;
    g_Q[dst + j + 16] = q1 * cs + q0 * sn;

    float k0 = g_k[src + j], k1 = g_k[src + j + 16];
    g_K[dst + j]      = k0 * cs - k1 * sn;
    g_K[dst + j + 16] = k1 * cs + k0 * sn;

    g_Q[dst + j + 32] = g_q[src + j + 32];
    g_Q[dst + j + 48] = g_q[src + j + 48];
    g_K[dst + j + 32] = g_k[src + j + 32];
    g_K[dst + j + 48] = g_k[src + j + 48];

    g_V[dst + j]      = g_v[src + j];
    g_V[dst + j + 16] = g_v[src + j + 16];
    g_V[dst + j + 32] = g_v[src + j + 32];
    g_V[dst + j + 48] = g_v[src + j + 48];
}

// ---------------------------------------------------------------------------
// Flash attention (fp32, causal). 64 Q rows x 64 K cols per tile, D=64.
// 256 threads: 16x16 grid, 4x4 microtile. Online softmax in registers.
// ---------------------------------------------------------------------------
#define ATT_SMEM_FLOATS (4096 + 4160 + 4096 + 4096)

__global__ __launch_bounds__(256) void attn_kernel()
{
    extern __shared__ __align__(16) float sm[];
    float* Qs  = sm;                 // 64*64
    float* KsT = sm + 4096;          // 64*65 (d-major, padded)
    float* Vs  = KsT + 4160;         // 64*64
    float* Ps  = Vs + 4096;          // 64*64

    const int bh = blockIdx.y;       // b*16 + h
    const int qb = blockIdx.x;       // query tile index

    const float* Qg = g_Q + (size_t)bh * TT * DD + (size_t)qb * 64 * DD;
    const float* Kg = g_K + (size_t)bh * TT * DD;
    const float* Vg = g_V + (size_t)bh * TT * DD;

    const int tid = threadIdx.x;
    const int tx = tid & 15, ty = tid >> 4;
    const int r0 = ty << 2, c0 = tx << 2;

#pragma unroll
    for (int i = 0; i < 4; i++) {
        int idx = tid + i * 256;
        int r = idx >> 4, d4 = (idx & 15) << 2;
        *(float4*)&Qs[r * 64 + d4] = *(const float4*)&Qg[r * 64 + d4];
    }

    float m[4], l[4], acc[4][4];
#pragma unroll
    for (int i = 0; i < 4; i++) {
        m[i] = -3.0e38f; l[i] = 0.f;
#pragma unroll
        for (int j = 0; j < 4; j++) acc[i][j] = 0.f;
    }

    for (int jt = 0; jt <= qb; jt++) {
        __syncthreads();
        const float* Kt = Kg + (size_t)jt * 64 * DD;
        const float* Vt = Vg + (size_t)jt * 64 * DD;
#pragma unroll
        for (int i = 0; i < 4; i++) {
            int idx = tid + i * 256;
            int r = idx >> 4, d4 = (idx & 15) << 2;
            float4 kv = *(const float4*)&Kt[r * 64 + d4];
            KsT[(d4 + 0) * 65 + r] = kv.x;
            KsT[(d4 + 1) * 65 + r] = kv.y;
            KsT[(d4 + 2) * 65 + r] = kv.z;
            KsT[(d4 + 3) * 65 + r] = kv.w;
            *(float4*)&Vs[r * 64 + d4] = *(const float4*)&Vt[r * 64 + d4];
        }
        __syncthreads();

        float s[4][4];
#pragma unroll
        for (int i = 0; i < 4; i++)
#pragma unroll
            for (int j = 0; j < 4; j++) s[i][j] = 0.f;

#pragma unroll 8
        for (int d = 0; d < 64; d++) {
            float qa[4], kb[4];
#pragma unroll
            for (int i = 0; i < 4; i++) qa[i] = Qs[(r0 + i) * 64 + d];
#pragma unroll
            for (int j = 0; j < 4; j++) kb[j] = KsT[d * 65 + c0 + j];
#pragma unroll
            for (int i = 0; i < 4; i++)
#pragma unroll
                for (int j = 0; j < 4; j++)
                    s[i][j] = fmaf(qa[i], kb[j], s[i][j]);
        }

        if (jt == qb) {
#pragma unroll
            for (int i = 0; i < 4; i++)
#pragma unroll
                for (int j = 0; j < 4; j++)
                    s[i][j] = (c0 + j <= r0 + i) ? s[i][j] * 0.125f : -1.0e30f;
        } else {
#pragma unroll
            for (int i = 0; i < 4; i++)
#pragma unroll
                for (int j = 0; j < 4; j++) s[i][j] *= 0.125f;
        }

#pragma unroll
        for (int i = 0; i < 4; i++) {
            float tm = fmaxf(fmaxf(s[i][0], s[i][1]), fmaxf(s[i][2], s[i][3]));
            tm = fmaxf(tm, __shfl_xor_sync(0xffffffffu, tm, 1));
            tm = fmaxf(tm, __shfl_xor_sync(0xffffffffu, tm, 2));
            tm = fmaxf(tm, __shfl_xor_sync(0xffffffffu, tm, 4));
            tm = fmaxf(tm, __shfl_xor_sync(0xffffffffu, tm, 8));
            float mn = fmaxf(m[i], tm);
            float rs = 0.f;
#pragma unroll
            for (int j = 0; j < 4; j++) {
                s[i][j] = __expf(s[i][j] - mn);
                rs += s[i][j];
            }
            rs += __shfl_xor_sync(0xffffffffu, rs, 1);
            rs += __shfl_xor_sync(0xffffffffu, rs, 2);
            rs += __shfl_xor_sync(0xffffffffu, rs, 4);
            rs += __shfl_xor_sync(0xffffffffu, rs, 8);
            float al = __expf(m[i] - mn);
            l[i] = l[i] * al + rs;
            m[i] = mn;
#pragma unroll
            for (int j = 0; j < 4; j++) acc[i][j] *= al;
#pragma unroll
            for (int j = 0; j < 4; j++) Ps[(r0 + i) * 64 + c0 + j] = s[i][j];
        }
        __syncthreads();

#pragma unroll 8
        for (int kk = 0; kk < 64; kk++) {
            float pr[4], vr[4];
#pragma unroll
            for (int i = 0; i < 4; i++) pr[i] = Ps[(r0 + i) * 64 + kk];
#pragma unroll
            for (int j = 0; j < 4; j++) vr[j] = Vs[kk * 64 + c0 + j];
#pragma unroll
            for (int i = 0; i < 4; i++)
#pragma unroll
                for (int j = 0; j < 4; j++)
                    acc[i][j] = fmaf(pr[i], vr[j], acc[i][j]);
        }
    }

    const int b = bh >> 4, h = bh & 15;
#pragma unroll
    for (int i = 0; i < 4; i++) {
        float invl = 1.f / l[i];
        size_t row = ((size_t)(b * TT + qb * 64 + r0 + i)) * CC + h * DD + c0;
#pragma unroll
        for (int j = 0; j < 4; j++)
            g_att[row + j] = acc[i][j] * invl;
    }
}

// ---------------------------------------------------------------------------
extern "C" void kernel_launch(void* const* d_in, const int* in_sizes, int n_in,
                              void* d_out, int out_size)
{
    const float* x  = (const float*)d_in[0];
    const float* Wq = (const float*)d_in[1];
    const float* bq = (const float*)d_in[2];
    const float* Wk = (const float*)d_in[3];
    const float* bk = (const float*)d_in[4];
    const float* Wv = (const float*)d_in[5];
    const float* bv = (const float*)d_in[6];
    const float* Wo = (const float*)d_in[7];
    const float* bo = (const float*)d_in[8];
    float* out = (float*)d_out;

    dim3 gg(CC / GBN, MM / GBM); // (8, 32)

    gemm_tf32<<<gg, 256>>>(x, Wq, bq, nullptr, 0, 0);
    gemm_tf32<<<gg, 256>>>(x, Wk, bk, nullptr, 0, 1);
    gemm_tf32<<<gg, 256>>>(x, Wv, bv, nullptr, 0, 2);

    rope_transpose_kernel<<<(BQ * HH * TT * 16) / 256, 256>>>();

    cudaFuncSetAttribute(attn_kernel,
                         cudaFuncAttributeMaxDynamicSharedMemorySize,
                         ATT_SMEM_FLOATS * sizeof(float));
    attn_kernel<<<dim3(TT / 64, BQ * HH), 256,
                  ATT_SMEM_FLOATS * sizeof(float)>>>();

    gemm_tf32<<<gg, 256>>>(nullptr, Wo, bo, out, 1, 3);
}

// round 6
// speedup vs baseline: 3.4376x; 1.9535x over previous
#include <cuda_runtime.h>
#include <cuda_bf16.h>
#include <math.h>

// Problem constants (fixed by the reference)
#define BQ 2
#define TT 2048
#define CC 1024
#define HH 16
#define DD 64
#define MM (BQ*TT)   // 4096 rows

// Scratch (device globals: allocation-free rule)
__device__ float g_q[(size_t)MM*CC];
__device__ float g_k[(size_t)MM*CC];
__device__ float g_v[(size_t)MM*CC];
__device__ float g_Q[(size_t)MM*CC];   // [B,H,T,D], rope applied
__device__ float g_K[(size_t)MM*CC];   // [B,H,T,D], rope applied
__device__ float g_V[(size_t)MM*CC];   // [B,H,T,D]
__device__ float g_att[(size_t)MM*CC]; // [B,T,C] attention output

__device__ __forceinline__ void cp16(void* dst, const void* src) {
    unsigned d = (unsigned)__cvta_generic_to_shared(dst);
    asm volatile("cp.async.cg.shared.global [%0], [%1], 16;\n" :: "r"(d), "l"(src));
}

__device__ __forceinline__ void mma_tf32(float c[4], const unsigned a[4],
                                         unsigned b0, unsigned b1) {
    asm volatile(
        "mma.sync.aligned.m16n8k8.row.col.f32.tf32.tf32.f32 "
        "{%0,%1,%2,%3}, {%4,%5,%6,%7}, {%8,%9}, {%0,%1,%2,%3};\n"
        : "+f"(c[0]), "+f"(c[1]), "+f"(c[2]), "+f"(c[3])
        : "r"(a[0]), "r"(a[1]), "r"(a[2]), "r"(a[3]), "r"(b0), "r"(b1));
}
#define CVT_TF32(x) asm volatile("cvt.rna.tf32.f32 %0, %0;\n" : "+r"(x))

// ---------------------------------------------------------------------------
// TF32 tensor-core GEMM: C[M,N] = A[M,K] @ W[K,N] + bias  (verified R4)
// ---------------------------------------------------------------------------
#define GBM 128
#define GBN 128
#define GBK 32
#define AS_STRIDE 36
#define BS_STRIDE 136

__global__ __launch_bounds__(256, 2) void gemm_tf32(
    const float* __restrict__ Aext, const float* __restrict__ W,
    const float* __restrict__ bias, float* __restrict__ Cext,
    int srcFlag, int dstFlag)
{
    const float* A = srcFlag ? g_att : Aext;
    float* C = (dstFlag == 0) ? g_q : (dstFlag == 1) ? g_k
             : (dstFlag == 2) ? g_v : Cext;

    __shared__ __align__(16) float As[GBM * AS_STRIDE];
    __shared__ __align__(16) float Bs[GBK * BS_STRIDE];

    const int tid  = threadIdx.x;
    const int lane = tid & 31;
    const int w    = tid >> 5;
    const int wr   = w >> 2;
    const int wc   = w & 3;
    const int bm   = blockIdx.y * GBM;
    const int bn   = blockIdx.x * GBN;

    float c[4][4][4];
#pragma unroll
    for (int mt = 0; mt < 4; mt++)
#pragma unroll
        for (int nt = 0; nt < 4; nt++)
#pragma unroll
            for (int j = 0; j < 4; j++) c[mt][nt][j] = 0.f;

    const int lq = lane >> 3;
    const int lr = lane & 7;
    const int a_row_off = wr * 64 + lr + 8 * (lq & 1);
    const int a_col_off = 4 * (lq >> 1);

    for (int kt = 0; kt < CC / GBK; kt++) {
#pragma unroll
        for (int i = 0; i < 4; i++) {
            int f = tid + i * 256;
            int row = f >> 3, c4 = f & 7;
            cp16(&As[row * AS_STRIDE + c4 * 4],
                 A + (size_t)(bm + row) * CC + kt * GBK + c4 * 4);
        }
#pragma unroll
        for (int i = 0; i < 4; i++) {
            int f = tid + i * 256;
            int k = f >> 5, c4 = f & 31;
            cp16(&Bs[k * BS_STRIDE + c4 * 4],
                 W + (size_t)(kt * GBK + k) * CC + bn + c4 * 4);
        }
        asm volatile("cp.async.commit_group;\n");
        asm volatile("cp.async.wait_group 0;\n");
        __syncthreads();

#pragma unroll
        for (int ks = 0; ks < 4; ks++) {
            unsigned a[4][4];
#pragma unroll
            for (int mt = 0; mt < 4; mt++) {
                unsigned addr = (unsigned)__cvta_generic_to_shared(
                    &As[(a_row_off + mt * 16) * AS_STRIDE + ks * 8 + a_col_off]);
                asm volatile(
                    "ldmatrix.sync.aligned.m8n8.x4.shared.b16 {%0,%1,%2,%3}, [%4];\n"
                    : "=r"(a[mt][0]), "=r"(a[mt][1]), "=r"(a[mt][2]), "=r"(a[mt][3])
                    : "r"(addr));
#pragma unroll
                for (int j = 0; j < 4; j++) CVT_TF32(a[mt][j]);
            }
#pragma unroll
            for (int nt = 0; nt < 4; nt++) {
                int n = wc * 32 + nt * 8 + (lane >> 2);
                int k = ks * 8 + (lane & 3);
                unsigned b0 = __float_as_uint(Bs[k * BS_STRIDE + n]);
                unsigned b1 = __float_as_uint(Bs[(k + 4) * BS_STRIDE + n]);
                CVT_TF32(b0);
                CVT_TF32(b1);
#pragma unroll
                for (int mt = 0; mt < 4; mt++)
                    mma_tf32(c[mt][nt], a[mt], b0, b1);
            }
        }
        __syncthreads();
    }

#pragma unroll
    for (int mt = 0; mt < 4; mt++) {
        int row = bm + wr * 64 + mt * 16 + (lane >> 2);
#pragma unroll
        for (int nt = 0; nt < 4; nt++) {
            int col = bn + wc * 32 + nt * 8 + 2 * (lane & 3);
            float b0 = bias[col], b1 = bias[col + 1];
            float2 v0 = make_float2(c[mt][nt][0] + b0, c[mt][nt][1] + b1);
            float2 v1 = make_float2(c[mt][nt][2] + b0, c[mt][nt][3] + b1);
            *(float2*)&C[(size_t)row * CC + col] = v0;
            *(float2*)&C[(size_t)(row + 8) * CC + col] = v1;
        }
    }
}

// ---------------------------------------------------------------------------
// RoPE + transpose [B,T,H,D] -> [B,H,T,D]. (verified R1/R4)
// ---------------------------------------------------------------------------
__global__ void rope_transpose_kernel()
{
    int idx = blockIdx.x * blockDim.x + threadIdx.x;
    if (idx >= BQ * HH * TT * 16) return;
    int j = idx & 15;
    int t = (idx >> 4) & (TT - 1);
    int h = (idx >> 15) & (HH - 1);
    int b = idx >> 19;

    const size_t src = ((size_t)(b * TT + t)) * CC + h * DD;
    const size_t dst = ((size_t)((b * HH + h) * TT + t)) * DD;

    float inv = exp2f(-(float)j * 0.8304820237218405f);
    float ang = (float)t * inv;
    float sn, cs;
    sincosf(ang, &sn, &cs);

    float q0 = g_q[src + j], q1 = g_q[src + j + 16];
    g_Q[dst + j]      = q0 * cs - q1 * sn;
    g_Q[dst + j + 16] = q1 * cs + q0 * sn;

    float k0 = g_k[src + j], k1 = g_k[src + j + 16];
    g_K[dst + j]      = k0 * cs - k1 * sn;
    g_K[dst + j + 16] = k1 * cs + k0 * sn;

    g_Q[dst + j + 32] = g_q[src + j + 32];
    g_Q[dst + j + 48] = g_q[src + j + 48];
    g_K[dst + j + 32] = g_k[src + j + 32];
    g_K[dst + j + 48] = g_k[src + j + 48];

    g_V[dst + j]      = g_v[src + j];
    g_V[dst + j + 16] = g_v[src + j + 16];
    g_V[dst + j + 32] = g_v[src + j + 32];
    g_V[dst + j + 48] = g_v[src + j + 48];
}

// ---------------------------------------------------------------------------
// Flash attention, tf32 tensor cores. 64 Q rows/CTA, 128 threads (4 warps,
// 16 rows each). KV tiles of 64. Online softmax on mma fragments.
// smem: Qs[64][68] Ks[64][68] Vs[64][72] Ps[64][68]
// ---------------------------------------------------------------------------
#define QS_STR 68
#define KS_STR 68
#define VS_STR 72
#define PS_STR 68
#define ATT_SMEM_FLOATS (64*QS_STR + 64*KS_STR + 64*VS_STR + 64*PS_STR)

__global__ __launch_bounds__(128) void attn_tc_kernel()
{
    extern __shared__ __align__(16) float sm[];
    float* Qs = sm;                       // 64 x 68
    float* Ks = Qs + 64 * QS_STR;         // 64 x 68
    float* Vs = Ks + 64 * KS_STR;         // 64 x 72
    float* Ps = Vs + 64 * VS_STR;         // 64 x 68

    const int bh = blockIdx.y;            // b*16 + h
    const int qb = blockIdx.x;
    const int tid  = threadIdx.x;
    const int lane = tid & 31;
    const int w    = tid >> 5;

    const float* Qg = g_Q + (size_t)bh * TT * DD + (size_t)qb * 64 * DD;
    const float* Kg = g_K + (size_t)bh * TT * DD;
    const float* Vg = g_V + (size_t)bh * TT * DD;

    // ---- load Q tile (once) ----
#pragma unroll
    for (int i = 0; i < 8; i++) {
        int idx = tid + i * 128;
        int r = idx >> 4, c4 = (idx & 15) << 2;
        *(float4*)&Qs[r * QS_STR + c4] = *(const float4*)&Qg[r * DD + c4];
    }
    __syncthreads();

    // ---- preload Q fragments (A-operand, verified ldmatrix-b16 pattern) ----
    const int lq = lane >> 3;
    const int lr = lane & 7;
    const int a_row = w * 16 + lr + 8 * (lq & 1);
    const int a_col = 4 * (lq >> 1);
    unsigned qf[8][4];
#pragma unroll
    for (int ks = 0; ks < 8; ks++) {
        unsigned addr = (unsigned)__cvta_generic_to_shared(
            &Qs[a_row * QS_STR + ks * 8 + a_col]);
        asm volatile(
            "ldmatrix.sync.aligned.m8n8.x4.shared.b16 {%0,%1,%2,%3}, [%4];\n"
            : "=r"(qf[ks][0]), "=r"(qf[ks][1]), "=r"(qf[ks][2]), "=r"(qf[ks][3])
            : "r"(addr));
#pragma unroll
        for (int j = 0; j < 4; j++) CVT_TF32(qf[ks][j]);
    }

    // B-fragment ldmatrix lane address base (K tile): x4 loads 2 n-tiles
    const int b_row = 8 * (lq >> 1) + lr;
    const int b_col = 4 * (lq & 1);

    // Row indices owned by this thread (fragment rows)
    const int fr = lane >> 2;            // 0..7
    const int fc = lane & 3;             // col group
    const int row0_l = w * 16 + fr;      // local row of c[.][0..1]
    const int row1_l = row0_l + 8;       // local row of c[.][2..3]

    float m0 = -3.0e38f, m1 = -3.0e38f, l0 = 0.f, l1 = 0.f;
    float o[8][4];
#pragma unroll
    for (int nt = 0; nt < 8; nt++)
#pragma unroll
        for (int j = 0; j < 4; j++) o[nt][j] = 0.f;

    for (int jt = 0; jt <= qb; jt++) {
        if (jt > 0) __syncthreads();     // all warps done reading Ks/Vs
        const float* Kt = Kg + (size_t)jt * 64 * DD;
        const float* Vt = Vg + (size_t)jt * 64 * DD;
#pragma unroll
        for (int i = 0; i < 8; i++) {
            int idx = tid + i * 128;
            int r = idx >> 4, c4 = (idx & 15) << 2;
            cp16(&Ks[r * KS_STR + c4], Kt + r * DD + c4);
            cp16(&Vs[r * VS_STR + c4], Vt + r * DD + c4);
        }
        asm volatile("cp.async.commit_group;\n");
        asm volatile("cp.async.wait_group 0;\n");
        __syncthreads();

        // ---- S = Q @ K^T : B-fragments via ldmatrix on Ks [kv][d] ----
        float c[8][4];
#pragma unroll
        for (int nt = 0; nt < 8; nt++)
#pragma unroll
            for (int j = 0; j < 4; j++) c[nt][j] = 0.f;

#pragma unroll
        for (int ks = 0; ks < 8; ks++) {
#pragma unroll
            for (int ntp = 0; ntp < 4; ntp++) {
                unsigned b[4];
                unsigned addr = (unsigned)__cvta_generic_to_shared(
                    &Ks[(ntp * 16 + b_row) * KS_STR + ks * 8 + b_col]);
                asm volatile(
                    "ldmatrix.sync.aligned.m8n8.x4.shared.b16 {%0,%1,%2,%3}, [%4];\n"
                    : "=r"(b[0]), "=r"(b[1]), "=r"(b[2]), "=r"(b[3])
                    : "r"(addr));
#pragma unroll
                for (int j = 0; j < 4; j++) CVT_TF32(b[j]);
                mma_tf32(c[2 * ntp],     qf[ks], b[0], b[1]);
                mma_tf32(c[2 * ntp + 1], qf[ks], b[2], b[3]);
            }
        }

        // ---- scale + causal mask ----
        if (jt == qb) {
#pragma unroll
            for (int nt = 0; nt < 8; nt++) {
                int col0 = nt * 8 + 2 * fc, col1 = col0 + 1;
                c[nt][0] = (col0 <= row0_l) ? c[nt][0] * 0.125f : -1.0e30f;
                c[nt][1] = (col1 <= row0_l) ? c[nt][1] * 0.125f : -1.0e30f;
                c[nt][2] = (col0 <= row1_l) ? c[nt][2] * 0.125f : -1.0e30f;
                c[nt][3] = (col1 <= row1_l) ? c[nt][3] * 0.125f : -1.0e30f;
            }
        } else {
#pragma unroll
            for (int nt = 0; nt < 8; nt++)
#pragma unroll
                for (int j = 0; j < 4; j++) c[nt][j] *= 0.125f;
        }

        // ---- online softmax (row groups = 4 lanes, xor 1/2) ----
        float mx0 = -3.0e38f, mx1 = -3.0e38f;
#pragma unroll
        for (int nt = 0; nt < 8; nt++) {
            mx0 = fmaxf(mx0, fmaxf(c[nt][0], c[nt][1]));
            mx1 = fmaxf(mx1, fmaxf(c[nt][2], c[nt][3]));
        }
        mx0 = fmaxf(mx0, __shfl_xor_sync(0xffffffffu, mx0, 1));
        mx0 = fmaxf(mx0, __shfl_xor_sync(0xffffffffu, mx0, 2));
        mx1 = fmaxf(mx1, __shfl_xor_sync(0xffffffffu, mx1, 1));
        mx1 = fmaxf(mx1, __shfl_xor_sync(0xffffffffu, mx1, 2));
        float mn0 = fmaxf(m0, mx0), mn1 = fmaxf(m1, mx1);
        float al0 = __expf(m0 - mn0), al1 = __expf(m1 - mn1);

        float rs0 = 0.f, rs1 = 0.f;
#pragma unroll
        for (int nt = 0; nt < 8; nt++) {
            c[nt][0] = __expf(c[nt][0] - mn0);
            c[nt][1] = __expf(c[nt][1] - mn0);
            c[nt][2] = __expf(c[nt][2] - mn1);
            c[nt][3] = __expf(c[nt][3] - mn1);
            rs0 += c[nt][0] + c[nt][1];
            rs1 += c[nt][2] + c[nt][3];
        }
        rs0 += __shfl_xor_sync(0xffffffffu, rs0, 1);
        rs0 += __shfl_xor_sync(0xffffffffu, rs0, 2);
        rs1 += __shfl_xor_sync(0xffffffffu, rs1, 1);
        rs1 += __shfl_xor_sync(0xffffffffu, rs1, 2);
        l0 = l0 * al0 + rs0; m0 = mn0;
        l1 = l1 * al1 + rs1; m1 = mn1;

#pragma unroll
        for (int nt = 0; nt < 8; nt++) {
            o[nt][0] *= al0; o[nt][1] *= al0;
            o[nt][2] *= al1; o[nt][3] *= al1;
            // stage P in per-warp smem slab (fragment relayout)
            *(float2*)&Ps[row0_l * PS_STR + nt * 8 + 2 * fc] =
                make_float2(c[nt][0], c[nt][1]);
            *(float2*)&Ps[row1_l * PS_STR + nt * 8 + 2 * fc] =
                make_float2(c[nt][2], c[nt][3]);
        }
        __syncwarp();

        // ---- O += P @ V : P via ldmatrix (A), V via conflict-free LDS (B) ----
#pragma unroll
        for (int ks = 0; ks < 8; ks++) {
            unsigned pf[4];
            unsigned addr = (unsigned)__cvta_generic_to_shared(
                &Ps[a_row * PS_STR + ks * 8 + a_col]);
            asm volatile(
                "ldmatrix.sync.aligned.m8n8.x4.shared.b16 {%0,%1,%2,%3}, [%4];\n"
                : "=r"(pf[0]), "=r"(pf[1]), "=r"(pf[2]), "=r"(pf[3])
                : "r"(addr));
#pragma unroll
            for (int j = 0; j < 4; j++) CVT_TF32(pf[j]);
            int k = ks * 8 + fc;
#pragma unroll
            for (int nt = 0; nt < 8; nt++) {
                int n = nt * 8 + fr;
                unsigned b0 = __float_as_uint(Vs[k * VS_STR + n]);
                unsigned b1 = __float_as_uint(Vs[(k + 4) * VS_STR + n]);
                CVT_TF32(b0);
                CVT_TF32(b1);
                mma_tf32(o[nt], pf, b0, b1);
            }
        }
        __syncwarp();   // Ps reads done before next iteration's overwrite
    }

    // ---- epilogue: normalize, write to g_att [B,T,C] ----
    const int b = bh >> 4, h = bh & 15;
    float inv0 = 1.f / l0, inv1 = 1.f / l1;
    size_t base0 = ((size_t)(b * TT + qb * 64 + row0_l)) * CC + h * DD;
    size_t base1 = ((size_t)(b * TT + qb * 64 + row1_l)) * CC + h * DD;
#pragma unroll
    for (int nt = 0; nt < 8; nt++) {
        int col = nt * 8 + 2 * fc;
        *(float2*)&g_att[base0 + col] =
            make_float2(o[nt][0] * inv0, o[nt][1] * inv0);
        *(float2*)&g_att[base1 + col] =
            make_float2(o[nt][2] * inv1, o[nt][3] * inv1);
    }
}

// ---------------------------------------------------------------------------
extern "C" void kernel_launch(void* const* d_in, const int* in_sizes, int n_in,
                              void* d_out, int out_size)
{
    const float* x  = (const float*)d_in[0];
    const float* Wq = (const float*)d_in[1];
    const float* bq = (const float*)d_in[2];
    const float* Wk = (const float*)d_in[3];
    const float* bk = (const float*)d_in[4];
    const float* Wv = (const float*)d_in[5];
    const float* bv = (const float*)d_in[6];
    const float* Wo = (const float*)d_in[7];
    const float* bo = (const float*)d_in[8];
    float* out = (float*)d_out;

    dim3 gg(CC / GBN, MM / GBM); // (8, 32)

    gemm_tf32<<<gg, 256>>>(x, Wq, bq, nullptr, 0, 0);
    gemm_tf32<<<gg, 256>>>(x, Wk, bk, nullptr, 0, 1);
    gemm_tf32<<<gg, 256>>>(x, Wv, bv, nullptr, 0, 2);

    rope_transpose_kernel<<<(BQ * HH * TT * 16) / 256, 256>>>();

    cudaFuncSetAttribute(attn_tc_kernel,
                         cudaFuncAttributeMaxDynamicSharedMemorySize,
                         ATT_SMEM_FLOATS * sizeof(float));
    attn_tc_kernel<<<dim3(TT / 64, BQ * HH), 128,
                     ATT_SMEM_FLOATS * sizeof(float)>>>();

    gemm_tf32<<<gg, 256>>>(nullptr, Wo, bo, out, 1, 3);
}